// round 15
// baseline (speedup 1.0000x reference)
#include <cuda_runtime.h>
#include <cuda_bf16.h>
#include <cstdint>

#define MAX_N 100000
#define MAX_E 1600000
#define HID   64
#define SCAN_TILE 1024
#define MAX_BLKS  ((MAX_N + SCAN_TILE - 1) / SCAN_TILE)

// Scratch: __device__ globals, referenced directly by symbol in device code.
__device__ __align__(16) float g_bufA[MAX_N * HID];
__device__ __align__(16) float g_bufB[MAX_N * HID];
__device__ float g_dis[MAX_N];
__device__ int   g_hist[MAX_N];      // edge in-degree (no self-loop)
__device__ int   g_rowptr[MAX_N];
__device__ int   g_cursor[MAX_N];
__device__ int   g_uhist[MAX_N];     // user_idx counts
__device__ int   g_urowptr[MAX_N];
__device__ int   g_ucursor[MAX_N];
__device__ int   g_unodes[MAX_N];    // CSR payload for user_idx
__device__ int   g_bsums[2 * MAX_BLKS + 2];
__device__ __align__(8) int2 g_erec[MAX_E];  // {src, norm bits}

// ---- tf32 / async-copy helpers -------------------------------------------
__device__ __forceinline__ unsigned int f2tf32(float f) {
    unsigned int u;
    asm("cvt.rna.tf32.f32 %0, %1;" : "=r"(u) : "f"(f));
    return u;
}
__device__ __forceinline__ void mma_tf32(float* d, const unsigned int* a,
                                         const unsigned int* b) {
    asm("mma.sync.aligned.m16n8k8.row.col.f32.tf32.tf32.f32 "
        "{%0,%1,%2,%3}, {%4,%5,%6,%7}, {%8,%9}, {%0,%1,%2,%3};"
        : "+f"(d[0]), "+f"(d[1]), "+f"(d[2]), "+f"(d[3])
        : "r"(a[0]), "r"(a[1]), "r"(a[2]), "r"(a[3]), "r"(b[0]), "r"(b[1]));
}
__device__ __forceinline__ void cp_async16(void* smem, const void* gmem) {
    unsigned int su = (unsigned int)__cvta_generic_to_shared(smem);
    asm volatile("cp.async.cg.shared.global [%0], [%1], 16;" :: "r"(su), "l"(gmem));
}
__device__ __forceinline__ void cp_commit() {
    asm volatile("cp.async.commit_group;");
}
template <int Nw>
__device__ __forceinline__ void cp_wait() {
    asm volatile("cp.async.wait_group %0;" :: "n"(Nw));
}

// ---------------------------------------------------------------------------
__global__ void k_zero_graph(int N) {
    int i = blockIdx.x * blockDim.x + threadIdx.x;
    if (i < N) { g_hist[i] = 0; g_cursor[i] = 0; g_uhist[i] = 0; g_ucursor[i] = 0; }
}

__global__ void k_histboth(const int* __restrict__ dst, const int* __restrict__ uidx,
                           int E, int N) {
    int i = blockIdx.x * blockDim.x + threadIdx.x;
    if (i < E)          atomicAdd(&g_hist[dst[i]], 1);
    else if (i < E + N) atomicAdd(&g_uhist[uidx[i - E]], 1);
}

// fused hierarchical scan, both CSRs in one grid; dis folded into which==0 pass
__global__ void __launch_bounds__(SCAN_TILE) k_scan_local(int nblk, int N) {
    __shared__ int sh[SCAN_TILE];
    int which = (blockIdx.x >= nblk) ? 1 : 0;
    int blk = blockIdx.x - which * nblk;
    const int* in = which ? g_uhist : g_hist;
    int* outp     = which ? g_urowptr : g_rowptr;
    int tid = threadIdx.x;
    int i = blk * SCAN_TILE + tid;
    int v = (i < N) ? in[i] : 0;
    sh[tid] = v;
    __syncthreads();
    for (int off = 1; off < SCAN_TILE; off <<= 1) {
        int t = (tid >= off) ? sh[tid - off] : 0;
        __syncthreads();
        sh[tid] += t;
        __syncthreads();
    }
    if (i < N) {
        outp[i] = sh[tid] - v;
        if (!which) g_dis[i] = rsqrtf((float)(v + 1));   // deg+1 (self-loop)
    }
    if (tid == SCAN_TILE - 1) g_bsums[blockIdx.x] = sh[tid];
}

// parallel block-sums scan: threads 0-127 do CSR-0 half, 128-255 do CSR-1 half
__global__ void k_scan_sums(int nblk) {
    __shared__ int sh[256];
    int t = threadIdx.x;
    int half = t >> 7;          // 0 or 1
    int i = t & 127;
    int v = (i < nblk) ? g_bsums[half * nblk + i] : 0;
    sh[t] = v;
    __syncthreads();
    for (int off = 1; off < 128; off <<= 1) {
        int tv = (i >= off) ? sh[t - off] : 0;
        __syncthreads();
        sh[t] += tv;
        __syncthreads();
    }
    if (i < nblk) g_bsums[half * nblk + i] = sh[t] - v;   // exclusive
}

__global__ void __launch_bounds__(SCAN_TILE) k_scan_add(int nblk, int N) {
    int which = (blockIdx.x >= nblk) ? 1 : 0;
    int blk = blockIdx.x - which * nblk;
    int* outp = which ? g_urowptr : g_rowptr;
    int i = blk * SCAN_TILE + threadIdx.x;
    if (i < N) outp[i] += g_bsums[blockIdx.x];
}

__global__ void k_scatterboth(const int* __restrict__ src, const int* __restrict__ dst,
                              const int* __restrict__ uidx, int E, int N) {
    int i = blockIdx.x * blockDim.x + threadIdx.x;
    if (i < E) {
        int s = src[i];
        int d = dst[i];
        int pos = g_rowptr[d] + atomicAdd(&g_cursor[d], 1);
        g_erec[pos] = make_int2(s, __float_as_int(g_dis[s] * g_dis[d]));
    } else if (i < E + N) {
        int n = i - E;
        int u = uidx[n];
        int pos = g_urowptr[u] + atomicAdd(&g_ucursor[u], 1);
        g_unodes[pos] = n;
    }
}

// ---------------------------------------------------------------------------
// Gather aggregation: warp per dst node. float4 lanes, half-warp edge pairing:
// lanes 0-15 gather edge e's row (16 x LDG.128 = 256B), lanes 16-31 edge e+1.
// One LDG warp-instruction serves TWO edges (LSU-instruction-bound kernel).
// Halves merged by shfl_xor(16). Writes g_bufB (+bias, relu, tf32 pre-round).
// ---------------------------------------------------------------------------
__global__ void __launch_bounds__(256) k_aggr(const float* __restrict__ bias,
                                              int N, int do_relu) {
    int d = (blockIdx.x * blockDim.x + threadIdx.x) >> 5;
    int lane = threadIdx.x & 31;
    if (d >= N) return;

    const float4* __restrict__ h4 = (const float4*)g_bufA;
    int c4 = lane & 15;          // 4-col group
    int half = lane >> 4;        // 0/1: even/odd edge of pair

    float4 acc = make_float4(0.f, 0.f, 0.f, 0.f);
    float sd = g_dis[d];
    float w = sd * sd;
    if (half == 0) {             // self term once
        float4 hv = h4[(size_t)d * 16 + c4];
        acc.x = w * hv.x; acc.y = w * hv.y; acc.z = w * hv.z; acc.w = w * hv.w;
    }

    int beg = g_rowptr[d];
    int deg = g_hist[d];
    for (int base = 0; base < deg; base += 32) {
        int n = deg - base; if (n > 32) n = 32;
        int2 r = g_erec[beg + base + ((lane < n) ? lane : 0)];
        int npair = (n + 1) >> 1;
#pragma unroll 4
        for (int j = 0; j < npair; ++j) {
            int e = 2 * j + half;                    // 0..31
            int   s    = __shfl_sync(0xffffffffu, r.x, e);
            float norm = __int_as_float(__shfl_sync(0xffffffffu, r.y, e));
            if (e >= n) norm = 0.f;                  // odd-tail mask (addr still valid)
            float4 hs = h4[(size_t)s * 16 + c4];
            acc.x = fmaf(norm, hs.x, acc.x);
            acc.y = fmaf(norm, hs.y, acc.y);
            acc.z = fmaf(norm, hs.z, acc.z);
            acc.w = fmaf(norm, hs.w, acc.w);
        }
    }

    // merge half-warp partials
    acc.x += __shfl_xor_sync(0xffffffffu, acc.x, 16);
    acc.y += __shfl_xor_sync(0xffffffffu, acc.y, 16);
    acc.z += __shfl_xor_sync(0xffffffffu, acc.z, 16);
    acc.w += __shfl_xor_sync(0xffffffffu, acc.w, 16);

    if (half == 0) {
        float4 bb = ((const float4*)bias)[c4];
        acc.x += bb.x; acc.y += bb.y; acc.z += bb.z; acc.w += bb.w;
        if (do_relu) {
            acc.x = fmaxf(acc.x, 0.f); acc.y = fmaxf(acc.y, 0.f);
            acc.z = fmaxf(acc.z, 0.f); acc.w = fmaxf(acc.w, 0.f);
            acc.x = __uint_as_float(f2tf32(acc.x));  // gemm2 truncation lossless
            acc.y = __uint_as_float(f2tf32(acc.y));
            acc.z = __uint_as_float(f2tf32(acc.z));
            acc.w = __uint_as_float(f2tf32(acc.w));
        }
        ((float4*)g_bufB)[(size_t)d * 16 + c4] = acc;
    }
}

// ---------------------------------------------------------------------------
// scatter-mean as gather: warp per user, same float4 half-warp pairing.
// ---------------------------------------------------------------------------
__global__ void __launch_bounds__(256) k_umean(float* __restrict__ out, int N) {
    int u = (blockIdx.x * blockDim.x + threadIdx.x) >> 5;
    int lane = threadIdx.x & 31;
    if (u >= N) return;
    const float4* __restrict__ h4 = (const float4*)g_bufB;
    int c4 = lane & 15;
    int half = lane >> 4;

    int cnt = g_uhist[u];
    float4 acc = make_float4(0.f, 0.f, 0.f, 0.f);
    int beg = g_urowptr[u];
    for (int base = 0; base < cnt; base += 32) {
        int n = cnt - base; if (n > 32) n = 32;
        int node_l = g_unodes[beg + base + ((lane < n) ? lane : 0)];
        int npair = (n + 1) >> 1;
#pragma unroll 4
        for (int j = 0; j < npair; ++j) {
            int e = 2 * j + half;
            int node = __shfl_sync(0xffffffffu, node_l, e);
            float m = (e < n) ? 1.f : 0.f;
            float4 hs = h4[(size_t)node * 16 + c4];
            acc.x = fmaf(m, hs.x, acc.x);
            acc.y = fmaf(m, hs.y, acc.y);
            acc.z = fmaf(m, hs.z, acc.z);
            acc.w = fmaf(m, hs.w, acc.w);
        }
    }
    acc.x += __shfl_xor_sync(0xffffffffu, acc.x, 16);
    acc.y += __shfl_xor_sync(0xffffffffu, acc.y, 16);
    acc.z += __shfl_xor_sync(0xffffffffu, acc.z, 16);
    acc.w += __shfl_xor_sync(0xffffffffu, acc.w, 16);
    if (half == 0) {
        float inv = (cnt > 0) ? 1.0f / (float)cnt : 0.f;
        acc.x *= inv; acc.y *= inv; acc.z *= inv; acc.w *= inv;
        ((float4*)out)[(size_t)u * 16 + c4] = acc;
    }
}

// ---------------------------------------------------------------------------
// tf32 tensor-core GEMM, cp.async double-buffered A staging (R13-verified).
// ---------------------------------------------------------------------------
template <int K>
__global__ void __launch_bounds__(256) gemm_kernel(const float* __restrict__ Ax,
                                                   const float* __restrict__ W,
                                                   int in_sel, int N) {
    const float* __restrict__ A = in_sel ? (const float*)g_bufB : Ax;
    __shared__ unsigned int Ws[K][72];                  // tf32 (rna) bits
    __shared__ __align__(16) unsigned int xs[2][128][36]; // raw fp32 bits (as tf32)

    int tid = threadIdx.x;
    int lane = tid & 31;
    int warp = tid >> 5;
    int warpRow = warp >> 1;            // 0..3 -> 32-row strip
    int warpCol = warp & 1;             // 0..1 -> 32-col strip
    int g = lane >> 2;                  // 0..7
    int tig = lane & 3;                 // 0..3
    int row0 = blockIdx.x * 128;
    int base_r = tid >> 3;              // 0..31 (staging row group)
    int kk = (tid & 7) * 4;             // 0..28 (staging k offset)

    // stage W (tf32, rna) once
    for (int i = tid; i < K * 64; i += 256)
        Ws[i >> 6][i & 63] = f2tf32(W[i]);

    const int NC = K / 32;
    // prefetch chunk 0 (OOB rows clamp to a valid address; results discarded)
#pragma unroll
    for (int it = 0; it < 4; ++it) {
        int r = base_r + it * 32;
        int row = row0 + r; if (row >= N) row = N - 1;
        cp_async16(&xs[0][r][kk], A + (size_t)row * K + kk);
    }
    cp_commit();

    float acc[2][4][4];
#pragma unroll
    for (int mi = 0; mi < 2; ++mi)
#pragma unroll
        for (int ni = 0; ni < 4; ++ni)
#pragma unroll
            for (int q = 0; q < 4; ++q) acc[mi][ni][q] = 0.f;

    for (int c = 0; c < NC; ++c) {
        if (c + 1 < NC) {                // prefetch next chunk; overlaps mma
#pragma unroll
            for (int it = 0; it < 4; ++it) {
                int r = base_r + it * 32;
                int row = row0 + r; if (row >= N) row = N - 1;
                cp_async16(&xs[(c + 1) & 1][r][kk],
                           A + (size_t)row * K + (c + 1) * 32 + kk);
            }
            cp_commit();
            cp_wait<1>();                // chunk c arrived (c+1 may be in flight)
        } else {
            cp_wait<0>();
        }
        __syncthreads();
        const unsigned int (*xb)[36] = xs[c & 1];
#pragma unroll
        for (int k8 = 0; k8 < 4; ++k8) {
            int kl = k8 * 8;             // k within chunk (xb)
            int kg = c * 32 + kl;        // k within W (Ws)
            unsigned int a[2][4];
#pragma unroll
            for (int mi = 0; mi < 2; ++mi) {
                int r = warpRow * 32 + mi * 16 + g;
                a[mi][0] = xb[r][kl + tig];
                a[mi][1] = xb[r + 8][kl + tig];
                a[mi][2] = xb[r][kl + tig + 4];
                a[mi][3] = xb[r + 8][kl + tig + 4];
            }
            unsigned int b[4][2];
#pragma unroll
            for (int ni = 0; ni < 4; ++ni) {
                int j = warpCol * 32 + ni * 8 + g;
                b[ni][0] = Ws[kg + tig][j];
                b[ni][1] = Ws[kg + tig + 4][j];
            }
#pragma unroll
            for (int mi = 0; mi < 2; ++mi)
#pragma unroll
                for (int ni = 0; ni < 4; ++ni)
                    mma_tf32(acc[mi][ni], a[mi], b[ni]);
        }
        __syncthreads();                 // buf consumed before it's re-filled
    }

    // epilogue: c0,c1 -> (row g, cols 2tig,2tig+1); c2,c3 -> row g+8
#pragma unroll
    for (int mi = 0; mi < 2; ++mi) {
#pragma unroll
        for (int ni = 0; ni < 4; ++ni) {
            int col = warpCol * 32 + ni * 8 + tig * 2;
            int rA = row0 + warpRow * 32 + mi * 16 + g;
            int rB = rA + 8;
            if (rA < N)
                *(float2*)(&g_bufA[(size_t)rA * 64 + col]) =
                    make_float2(acc[mi][ni][0], acc[mi][ni][1]);
            if (rB < N)
                *(float2*)(&g_bufA[(size_t)rB * 64 + col]) =
                    make_float2(acc[mi][ni][2], acc[mi][ni][3]);
        }
    }
}

// ---------------------------------------------------------------------------
static inline int cdiv(int a, int b) { return (a + b - 1) / b; }

extern "C" void kernel_launch(void* const* d_in, const int* in_sizes, int n_in,
                              void* d_out, int out_size) {
    const float* x    = (const float*)d_in[0];
    const int*   ei   = (const int*)d_in[1];      // int32 per harness dtype contract
    const int*   uidx = (const int*)d_in[2];
    const float* W1   = (const float*)d_in[3];
    const float* b1   = (const float*)d_in[4];
    const float* W2   = (const float*)d_in[5];
    const float* b2   = (const float*)d_in[6];
    float* out = (float*)d_out;

    const int N = in_sizes[2];
    const int E = in_sizes[1] / 2;
    const int* src = ei;
    const int* dst = ei + E;

    const int TB = 256;
    const int nblk = cdiv(N, SCAN_TILE);

    // One-time stream/event setup (first call is the uncaptured correctness
    // run; no device memory is allocated by these).
    static cudaStream_t s2 = nullptr;
    static cudaEvent_t evFork = nullptr, evJoin = nullptr;
    if (s2 == nullptr) {
        cudaStreamCreateWithFlags(&s2, cudaStreamNonBlocking);
        cudaEventCreateWithFlags(&evFork, cudaEventDisableTiming);
        cudaEventCreateWithFlags(&evJoin, cudaEventDisableTiming);
    }

    // ---- fork: CSR build on s2, gemm1 on default stream (independent) ----
    cudaEventRecord(evFork, 0);
    cudaStreamWaitEvent(s2, evFork, 0);

    k_zero_graph<<<cdiv(N, TB), TB, 0, s2>>>(N);
    k_histboth<<<cdiv(E + N, TB), TB, 0, s2>>>(dst, uidx, E, N);
    k_scan_local<<<2 * nblk, SCAN_TILE, 0, s2>>>(nblk, N);
    k_scan_sums<<<1, 256, 0, s2>>>(nblk);
    k_scan_add<<<2 * nblk, SCAN_TILE, 0, s2>>>(nblk, N);
    k_scatterboth<<<cdiv(E + N, TB), TB, 0, s2>>>(src, dst, uidx, E, N);
    cudaEventRecord(evJoin, s2);

    gemm_kernel<128><<<cdiv(N, 128), 256>>>(x, W1, 0, N);   // x -> bufA

    cudaStreamWaitEvent(0, evJoin, 0);                      // join

    // ---- layer-1 aggregate (bufA -> bufB, +b1, relu, tf32-rounded) ----
    k_aggr<<<cdiv(N * 32, TB), TB>>>(b1, N, 1);
    // ---- layer 2 ----
    gemm_kernel<64><<<cdiv(N, 128), 256>>>(x, W2, 1, N);    // bufB -> bufA
    k_aggr<<<cdiv(N * 32, TB), TB>>>(b2, N, 0);             // bufA -> bufB
    // ---- scatter-mean (bufB -> out) ----
    k_umean<<<cdiv(N * 32, TB), TB>>>(out, N);
}

// round 16
// speedup vs baseline: 1.0090x; 1.0090x over previous
#include <cuda_runtime.h>
#include <cuda_bf16.h>
#include <cstdint>

#define MAX_N 100000
#define MAX_E 1600000
#define HID   64
#define SCAN_TILE 1024
#define MAX_BLKS  ((MAX_N + SCAN_TILE - 1) / SCAN_TILE)

// Scratch: __device__ globals, referenced directly by symbol in device code.
__device__ __align__(16) float g_bufA[MAX_N * HID];
__device__ __align__(16) float g_bufB[MAX_N * HID];
__device__ float g_dis[MAX_N];
__device__ int   g_hist[MAX_N];      // edge in-degree (no self-loop)
__device__ int   g_rowptr[MAX_N];
__device__ int   g_cursor[MAX_N];
__device__ int   g_uhist[MAX_N];     // user_idx counts
__device__ int   g_urowptr[MAX_N];
__device__ int   g_ucursor[MAX_N];
__device__ int   g_unodes[MAX_N];    // CSR payload for user_idx
__device__ int   g_bsums[2 * MAX_BLKS + 2];
__device__ __align__(8) int2 g_erec[MAX_E];  // {src, norm bits}

// ---- tf32 / async-copy helpers -------------------------------------------
__device__ __forceinline__ unsigned int f2tf32(float f) {
    unsigned int u;
    asm("cvt.rna.tf32.f32 %0, %1;" : "=r"(u) : "f"(f));
    return u;
}
__device__ __forceinline__ void mma_tf32(float* d, const unsigned int* a,
                                         const unsigned int* b) {
    asm("mma.sync.aligned.m16n8k8.row.col.f32.tf32.tf32.f32 "
        "{%0,%1,%2,%3}, {%4,%5,%6,%7}, {%8,%9}, {%0,%1,%2,%3};"
        : "+f"(d[0]), "+f"(d[1]), "+f"(d[2]), "+f"(d[3])
        : "r"(a[0]), "r"(a[1]), "r"(a[2]), "r"(a[3]), "r"(b[0]), "r"(b[1]));
}
__device__ __forceinline__ void cp_async16(void* smem, const void* gmem) {
    unsigned int su = (unsigned int)__cvta_generic_to_shared(smem);
    asm volatile("cp.async.cg.shared.global [%0], [%1], 16;" :: "r"(su), "l"(gmem));
}
__device__ __forceinline__ void cp_commit() {
    asm volatile("cp.async.commit_group;");
}
template <int Nw>
__device__ __forceinline__ void cp_wait() {
    asm volatile("cp.async.wait_group %0;" :: "n"(Nw));
}

// ---------------------------------------------------------------------------
__global__ void k_zero_graph(int N) {
    int i = blockIdx.x * blockDim.x + threadIdx.x;
    if (i < N) { g_hist[i] = 0; g_cursor[i] = 0; g_uhist[i] = 0; g_ucursor[i] = 0; }
}

__global__ void k_histboth(const int* __restrict__ dst, const int* __restrict__ uidx,
                           int E, int N) {
    int i = blockIdx.x * blockDim.x + threadIdx.x;
    if (i < E)          atomicAdd(&g_hist[dst[i]], 1);
    else if (i < E + N) atomicAdd(&g_uhist[uidx[i - E]], 1);
}

// fused hierarchical scan, both CSRs in one grid; dis folded into which==0 pass
__global__ void __launch_bounds__(SCAN_TILE) k_scan_local(int nblk, int N) {
    __shared__ int sh[SCAN_TILE];
    int which = (blockIdx.x >= nblk) ? 1 : 0;
    int blk = blockIdx.x - which * nblk;
    const int* in = which ? g_uhist : g_hist;
    int* outp     = which ? g_urowptr : g_rowptr;
    int tid = threadIdx.x;
    int i = blk * SCAN_TILE + tid;
    int v = (i < N) ? in[i] : 0;
    sh[tid] = v;
    __syncthreads();
    for (int off = 1; off < SCAN_TILE; off <<= 1) {
        int t = (tid >= off) ? sh[tid - off] : 0;
        __syncthreads();
        sh[tid] += t;
        __syncthreads();
    }
    if (i < N) {
        outp[i] = sh[tid] - v;
        if (!which) g_dis[i] = rsqrtf((float)(v + 1));   // deg+1 (self-loop)
    }
    if (tid == SCAN_TILE - 1) g_bsums[blockIdx.x] = sh[tid];
}

// fused block-sums scan + add: every block redundantly scans the (2*nblk)-entry
// bsums array in smem (nblk <= 128), then adds its own exclusive offset.
// Replaces the separate single-block k_scan_sums kernel.
__global__ void __launch_bounds__(SCAN_TILE) k_scan_add(int nblk, int N) {
    __shared__ int sh[256];
    __shared__ int ex[256];
    int t = threadIdx.x;
    int v256 = 0;
    if (t < 256) {
        int half = t >> 7, i = t & 127;
        v256 = (i < nblk) ? g_bsums[half * nblk + i] : 0;
        sh[t] = v256;
    }
    __syncthreads();
    for (int off = 1; off < 128; off <<= 1) {
        int tv = 0;
        if (t < 256 && (t & 127) >= off) tv = sh[t - off];
        __syncthreads();
        if (t < 256) sh[t] += tv;
        __syncthreads();
    }
    if (t < 256) ex[t] = sh[t] - v256;    // exclusive prefix per half
    __syncthreads();

    int which = (blockIdx.x >= nblk) ? 1 : 0;
    int blk = blockIdx.x - which * nblk;
    int off = ex[which * 128 + blk];
    int* outp = which ? g_urowptr : g_rowptr;
    int i = blk * SCAN_TILE + t;
    if (i < N) outp[i] += off;
}

__global__ void k_scatterboth(const int* __restrict__ src, const int* __restrict__ dst,
                              const int* __restrict__ uidx, int E, int N) {
    int i = blockIdx.x * blockDim.x + threadIdx.x;
    if (i < E) {
        int s = src[i];
        int d = dst[i];
        int pos = g_rowptr[d] + atomicAdd(&g_cursor[d], 1);
        g_erec[pos] = make_int2(s, __float_as_int(g_dis[s] * g_dis[d]));
    } else if (i < E + N) {
        int n = i - E;
        int u = uidx[n];
        int pos = g_urowptr[u] + atomicAdd(&g_ucursor[u], 1);
        g_unodes[pos] = n;
    }
}

// ---------------------------------------------------------------------------
// Gather aggregation (R14-verified form): warp per dst node, lane owns cols
// {2*lane, 2*lane+1} (float2). Edge records read cooperatively and
// shuffle-broadcast. Reads g_bufA, writes g_bufB. Layer 1 pre-rounds to tf32.
// ---------------------------------------------------------------------------
__global__ void __launch_bounds__(256) k_aggr(const float* __restrict__ bias,
                                              int N, int do_relu) {
    int d = (blockIdx.x * blockDim.x + threadIdx.x) >> 5;
    int lane = threadIdx.x & 31;
    if (d >= N) return;

    const float2* __restrict__ h2 = (const float2*)g_bufA;

    float sd = g_dis[d];
    float w = sd * sd;
    float2 hv = h2[(size_t)d * 32 + lane];
    float ax = w * hv.x;
    float ay = w * hv.y;

    int beg = g_rowptr[d];
    int deg = g_hist[d];
    for (int base = 0; base < deg; base += 32) {
        int n = deg - base; if (n > 32) n = 32;
        int2 r = g_erec[beg + base + ((lane < n) ? lane : 0)];
#pragma unroll 8
        for (int j = 0; j < n; ++j) {
            int   s    = __shfl_sync(0xffffffffu, r.x, j);
            float norm = __int_as_float(__shfl_sync(0xffffffffu, r.y, j));
            float2 hs = h2[(size_t)s * 32 + lane];
            ax = fmaf(norm, hs.x, ax);
            ay = fmaf(norm, hs.y, ay);
        }
    }

    float2 bb = ((const float2*)bias)[lane];
    ax += bb.x; ay += bb.y;
    if (do_relu) {
        ax = fmaxf(ax, 0.f); ay = fmaxf(ay, 0.f);
        ax = __uint_as_float(f2tf32(ax));   // pre-round: gemm2 truncation lossless
        ay = __uint_as_float(f2tf32(ay));
    }
    ((float2*)g_bufB)[(size_t)d * 32 + lane] = make_float2(ax, ay);
}

// ---------------------------------------------------------------------------
// scatter-mean as gather: warp per user u; float2 lanes; plain store to d_out.
// ---------------------------------------------------------------------------
__global__ void __launch_bounds__(256) k_umean(float* __restrict__ out, int N) {
    int u = (blockIdx.x * blockDim.x + threadIdx.x) >> 5;
    int lane = threadIdx.x & 31;
    if (u >= N) return;
    const float2* __restrict__ h2 = (const float2*)g_bufB;
    int cnt = g_uhist[u];
    float ax = 0.f, ay = 0.f;
    int beg = g_urowptr[u];
    for (int base = 0; base < cnt; base += 32) {
        int n = cnt - base; if (n > 32) n = 32;
        int node_l = g_unodes[beg + base + ((lane < n) ? lane : 0)];
#pragma unroll 8
        for (int j = 0; j < n; ++j) {
            int node = __shfl_sync(0xffffffffu, node_l, j);
            float2 hs = h2[(size_t)node * 32 + lane];
            ax += hs.x; ay += hs.y;
        }
    }
    float inv = (cnt > 0) ? 1.0f / (float)cnt : 0.f;
    ((float2*)out)[(size_t)u * 32 + lane] = make_float2(ax * inv, ay * inv);
}

// ---------------------------------------------------------------------------
// tf32 tensor-core GEMM, cp.async double-buffered A staging (R13-verified).
// ---------------------------------------------------------------------------
template <int K>
__global__ void __launch_bounds__(256) gemm_kernel(const float* __restrict__ Ax,
                                                   const float* __restrict__ W,
                                                   int in_sel, int N) {
    const float* __restrict__ A = in_sel ? (const float*)g_bufB : Ax;
    __shared__ unsigned int Ws[K][72];                  // tf32 (rna) bits
    __shared__ __align__(16) unsigned int xs[2][128][36]; // raw fp32 bits (as tf32)

    int tid = threadIdx.x;
    int lane = tid & 31;
    int warp = tid >> 5;
    int warpRow = warp >> 1;            // 0..3 -> 32-row strip
    int warpCol = warp & 1;             // 0..1 -> 32-col strip
    int g = lane >> 2;                  // 0..7
    int tig = lane & 3;                 // 0..3
    int row0 = blockIdx.x * 128;
    int base_r = tid >> 3;              // 0..31 (staging row group)
    int kk = (tid & 7) * 4;             // 0..28 (staging k offset)

    // stage W (tf32, rna) once
    for (int i = tid; i < K * 64; i += 256)
        Ws[i >> 6][i & 63] = f2tf32(W[i]);

    const int NC = K / 32;
    // prefetch chunk 0 (OOB rows clamp to a valid address; results discarded)
#pragma unroll
    for (int it = 0; it < 4; ++it) {
        int r = base_r + it * 32;
        int row = row0 + r; if (row >= N) row = N - 1;
        cp_async16(&xs[0][r][kk], A + (size_t)row * K + kk);
    }
    cp_commit();

    float acc[2][4][4];
#pragma unroll
    for (int mi = 0; mi < 2; ++mi)
#pragma unroll
        for (int ni = 0; ni < 4; ++ni)
#pragma unroll
            for (int q = 0; q < 4; ++q) acc[mi][ni][q] = 0.f;

    for (int c = 0; c < NC; ++c) {
        if (c + 1 < NC) {                // prefetch next chunk; overlaps mma
#pragma unroll
            for (int it = 0; it < 4; ++it) {
                int r = base_r + it * 32;
                int row = row0 + r; if (row >= N) row = N - 1;
                cp_async16(&xs[(c + 1) & 1][r][kk],
                           A + (size_t)row * K + (c + 1) * 32 + kk);
            }
            cp_commit();
            cp_wait<1>();                // chunk c arrived (c+1 may be in flight)
        } else {
            cp_wait<0>();
        }
        __syncthreads();
        const unsigned int (*xb)[36] = xs[c & 1];
#pragma unroll
        for (int k8 = 0; k8 < 4; ++k8) {
            int kl = k8 * 8;             // k within chunk (xb)
            int kg = c * 32 + kl;        // k within W (Ws)
            unsigned int a[2][4];
#pragma unroll
            for (int mi = 0; mi < 2; ++mi) {
                int r = warpRow * 32 + mi * 16 + g;
                a[mi][0] = xb[r][kl + tig];
                a[mi][1] = xb[r + 8][kl + tig];
                a[mi][2] = xb[r][kl + tig + 4];
                a[mi][3] = xb[r + 8][kl + tig + 4];
            }
            unsigned int b[4][2];
#pragma unroll
            for (int ni = 0; ni < 4; ++ni) {
                int j = warpCol * 32 + ni * 8 + g;
                b[ni][0] = Ws[kg + tig][j];
                b[ni][1] = Ws[kg + tig + 4][j];
            }
#pragma unroll
            for (int mi = 0; mi < 2; ++mi)
#pragma unroll
                for (int ni = 0; ni < 4; ++ni)
                    mma_tf32(acc[mi][ni], a[mi], b[ni]);
        }
        __syncthreads();                 // buf consumed before it's re-filled
    }

    // epilogue: c0,c1 -> (row g, cols 2tig,2tig+1); c2,c3 -> row g+8
#pragma unroll
    for (int mi = 0; mi < 2; ++mi) {
#pragma unroll
        for (int ni = 0; ni < 4; ++ni) {
            int col = warpCol * 32 + ni * 8 + tig * 2;
            int rA = row0 + warpRow * 32 + mi * 16 + g;
            int rB = rA + 8;
            if (rA < N)
                *(float2*)(&g_bufA[(size_t)rA * 64 + col]) =
                    make_float2(acc[mi][ni][0], acc[mi][ni][1]);
            if (rB < N)
                *(float2*)(&g_bufA[(size_t)rB * 64 + col]) =
                    make_float2(acc[mi][ni][2], acc[mi][ni][3]);
        }
    }
}

// ---------------------------------------------------------------------------
static inline int cdiv(int a, int b) { return (a + b - 1) / b; }

extern "C" void kernel_launch(void* const* d_in, const int* in_sizes, int n_in,
                              void* d_out, int out_size) {
    const float* x    = (const float*)d_in[0];
    const int*   ei   = (const int*)d_in[1];      // int32 per harness dtype contract
    const int*   uidx = (const int*)d_in[2];
    const float* W1   = (const float*)d_in[3];
    const float* b1   = (const float*)d_in[4];
    const float* W2   = (const float*)d_in[5];
    const float* b2   = (const float*)d_in[6];
    float* out = (float*)d_out;

    const int N = in_sizes[2];
    const int E = in_sizes[1] / 2;
    const int* src = ei;
    const int* dst = ei + E;

    const int TB = 256;
    const int nblk = cdiv(N, SCAN_TILE);

    // One-time stream/event setup (first call is the uncaptured correctness
    // run; no device memory is allocated by these).
    static cudaStream_t s2 = nullptr;
    static cudaEvent_t evFork = nullptr, evJoin = nullptr;
    if (s2 == nullptr) {
        cudaStreamCreateWithFlags(&s2, cudaStreamNonBlocking);
        cudaEventCreateWithFlags(&evFork, cudaEventDisableTiming);
        cudaEventCreateWithFlags(&evJoin, cudaEventDisableTiming);
    }

    // ---- fork: CSR build on s2, gemm1 on default stream (independent) ----
    cudaEventRecord(evFork, 0);
    cudaStreamWaitEvent(s2, evFork, 0);

    k_zero_graph<<<cdiv(N, TB), TB, 0, s2>>>(N);
    k_histboth<<<cdiv(E + N, TB), TB, 0, s2>>>(dst, uidx, E, N);
    k_scan_local<<<2 * nblk, SCAN_TILE, 0, s2>>>(nblk, N);
    k_scan_add<<<2 * nblk, SCAN_TILE, 0, s2>>>(nblk, N);
    k_scatterboth<<<cdiv(E + N, TB), TB, 0, s2>>>(src, dst, uidx, E, N);
    cudaEventRecord(evJoin, s2);

    gemm_kernel<128><<<cdiv(N, 128), 256>>>(x, W1, 0, N);   // x -> bufA

    cudaStreamWaitEvent(0, evJoin, 0);                      // join

    // ---- layer-1 aggregate (bufA -> bufB, +b1, relu, tf32-rounded) ----
    k_aggr<<<cdiv(N * 32, TB), TB>>>(b1, N, 1);
    // ---- layer 2 ----
    gemm_kernel<64><<<cdiv(N, 128), 256>>>(x, W2, 1, N);    // bufB -> bufA
    k_aggr<<<cdiv(N * 32, TB), TB>>>(b2, N, 0);             // bufA -> bufB
    // ---- scatter-mean (bufB -> out) ----
    k_umean<<<cdiv(N * 32, TB), TB>>>(out, N);
}

// round 17
// speedup vs baseline: 1.0472x; 1.0378x over previous
#include <cuda_runtime.h>
#include <cuda_bf16.h>
#include <cstdint>

#define MAX_N 100000
#define MAX_E 1600000
#define HID   64
#define SCAN_TILE 1024
#define MAX_BLKS  ((MAX_N + SCAN_TILE - 1) / SCAN_TILE)

// Scratch: __device__ globals (zero-initialized at module load; k_umean
// re-zeroes the histogram/cursor/flag arrays for the next replay).
__device__ __align__(16) float g_bufA[MAX_N * HID];
__device__ __align__(16) float g_bufB[MAX_N * HID];
__device__ float g_dis[MAX_N];
__device__ int   g_hist[MAX_N];      // edge in-degree (zeroed by k_umean)
__device__ int   g_rowptr[MAX_N];
__device__ int   g_cursor[MAX_N];
__device__ int   g_uhist[MAX_N];     // user_idx counts (zeroed by k_umean)
__device__ int   g_urowptr[MAX_N];
__device__ int   g_ucursor[MAX_N];
__device__ int   g_unodes[MAX_N];    // CSR payload for user_idx
__device__ unsigned long long g_bpack[2 * MAX_BLKS + 2];  // (total<<32)|1 per scan block
__device__ __align__(8) int2 g_erec[MAX_E];  // {src, norm bits}

// ---- tf32 / async-copy helpers -------------------------------------------
__device__ __forceinline__ unsigned int f2tf32(float f) {
    unsigned int u;
    asm("cvt.rna.tf32.f32 %0, %1;" : "=r"(u) : "f"(f));
    return u;
}
__device__ __forceinline__ void mma_tf32(float* d, const unsigned int* a,
                                         const unsigned int* b) {
    asm("mma.sync.aligned.m16n8k8.row.col.f32.tf32.tf32.f32 "
        "{%0,%1,%2,%3}, {%4,%5,%6,%7}, {%8,%9}, {%0,%1,%2,%3};"
        : "+f"(d[0]), "+f"(d[1]), "+f"(d[2]), "+f"(d[3])
        : "r"(a[0]), "r"(a[1]), "r"(a[2]), "r"(a[3]), "r"(b[0]), "r"(b[1]));
}
__device__ __forceinline__ void cp_async16(void* smem, const void* gmem) {
    unsigned int su = (unsigned int)__cvta_generic_to_shared(smem);
    asm volatile("cp.async.cg.shared.global [%0], [%1], 16;" :: "r"(su), "l"(gmem));
}
__device__ __forceinline__ void cp_commit() {
    asm volatile("cp.async.commit_group;");
}
template <int Nw>
__device__ __forceinline__ void cp_wait() {
    asm volatile("cp.async.wait_group %0;" :: "n"(Nw));
}

// ---------------------------------------------------------------------------
__global__ void k_histboth(const int* __restrict__ dst, const int* __restrict__ uidx,
                           int E, int N) {
    int i = blockIdx.x * blockDim.x + threadIdx.x;
    if (i < E)          atomicAdd(&g_hist[dst[i]], 1);
    else if (i < E + N) atomicAdd(&g_uhist[uidx[i - E]], 1);
}

// Single-pass scan (both CSR halves in one grid) with safe lookback.
// Each block: tile scan -> unconditional publish of its total (packed with a
// ready-bit; publish depends on NO other block => deadlock-impossible) ->
// warp-0 gathers predecessor totals -> write rowptr (+dis on edge half).
__global__ void __launch_bounds__(SCAN_TILE) k_scan(int nblk, int N) {
    __shared__ int sh[SCAN_TILE];
    __shared__ int sh_off;
    int which = (blockIdx.x >= nblk) ? 1 : 0;
    int blk = blockIdx.x - which * nblk;
    const int* in = which ? g_uhist : g_hist;
    int* outp     = which ? g_urowptr : g_rowptr;
    int tid = threadIdx.x;
    int i = blk * SCAN_TILE + tid;
    int v = (i < N) ? in[i] : 0;
    sh[tid] = v;
    __syncthreads();
    for (int off = 1; off < SCAN_TILE; off <<= 1) {
        int t = (tid >= off) ? sh[tid - off] : 0;
        __syncthreads();
        sh[tid] += t;
        __syncthreads();
    }
    // publish this block's total (value<<32 | ready)
    if (tid == SCAN_TILE - 1)
        atomicExch(&g_bpack[blockIdx.x],
                   ((unsigned long long)(unsigned int)sh[tid] << 32) | 1ULL);
    // lookback: warp 0 sums all predecessor totals in this half
    if (tid < 32) {
        int off = 0;
        int start = which * nblk;
        for (int b0 = start; b0 < blockIdx.x; b0 += 32) {
            int b = b0 + tid;
            int val = 0;
            if (b < blockIdx.x) {
                unsigned long long w;
                do { w = atomicAdd(&g_bpack[b], 0ULL); } while (w == 0ULL);
                val = (int)(w >> 32);
            }
#pragma unroll
            for (int s = 16; s; s >>= 1) val += __shfl_xor_sync(0xffffffffu, val, s);
            off += val;
        }
        if (tid == 0) sh_off = off;
    }
    __syncthreads();
    if (i < N) {
        outp[i] = sh[tid] - v + sh_off;               // exclusive prefix
        if (!which) g_dis[i] = rsqrtf((float)(v + 1)); // deg+1 (self-loop)
    }
}

__global__ void k_scatterboth(const int* __restrict__ src, const int* __restrict__ dst,
                              const int* __restrict__ uidx, int E, int N) {
    int i = blockIdx.x * blockDim.x + threadIdx.x;
    if (i < E) {
        int s = src[i];
        int d = dst[i];
        int pos = g_rowptr[d] + atomicAdd(&g_cursor[d], 1);
        g_erec[pos] = make_int2(s, __float_as_int(g_dis[s] * g_dis[d]));
    } else if (i < E + N) {
        int n = i - E;
        int u = uidx[n];
        int pos = g_urowptr[u] + atomicAdd(&g_ucursor[u], 1);
        g_unodes[pos] = n;
    }
}

// ---------------------------------------------------------------------------
// Gather aggregation (R14-verified inner loop): warp per dst node, lane owns
// cols {2*lane, 2*lane+1}. Degree derived from rowptr difference (no hist
// read). Reads g_bufA, writes g_bufB. Layer 1 pre-rounds to tf32.
// ---------------------------------------------------------------------------
__global__ void __launch_bounds__(256) k_aggr(const float* __restrict__ bias,
                                              int N, int E, int do_relu) {
    int d = (blockIdx.x * blockDim.x + threadIdx.x) >> 5;
    int lane = threadIdx.x & 31;
    if (d >= N) return;

    const float2* __restrict__ h2 = (const float2*)g_bufA;

    float sd = g_dis[d];
    float w = sd * sd;
    float2 hv = h2[(size_t)d * 32 + lane];
    float ax = w * hv.x;
    float ay = w * hv.y;

    int beg = g_rowptr[d];
    int end = (d + 1 < N) ? g_rowptr[d + 1] : E;
    int deg = end - beg;
    for (int base = 0; base < deg; base += 32) {
        int n = deg - base; if (n > 32) n = 32;
        int2 r = g_erec[beg + base + ((lane < n) ? lane : 0)];
#pragma unroll 8
        for (int j = 0; j < n; ++j) {
            int   s    = __shfl_sync(0xffffffffu, r.x, j);
            float norm = __int_as_float(__shfl_sync(0xffffffffu, r.y, j));
            float2 hs = h2[(size_t)s * 32 + lane];
            ax = fmaf(norm, hs.x, ax);
            ay = fmaf(norm, hs.y, ay);
        }
    }

    float2 bb = ((const float2*)bias)[lane];
    ax += bb.x; ay += bb.y;
    if (do_relu) {
        ax = fmaxf(ax, 0.f); ay = fmaxf(ay, 0.f);
        ax = __uint_as_float(f2tf32(ax));   // pre-round: gemm2 truncation lossless
        ay = __uint_as_float(f2tf32(ay));
    }
    ((float2*)g_bufB)[(size_t)d * 32 + lane] = make_float2(ax, ay);
}

// ---------------------------------------------------------------------------
// scatter-mean as gather: warp per user u (count from urowptr difference).
// Also re-zeroes the histogram/cursor/flag scratch for the next replay
// (none of those arrays are read by this kernel).
// ---------------------------------------------------------------------------
__global__ void __launch_bounds__(256) k_umean(float* __restrict__ out, int N) {
    int g = blockIdx.x * blockDim.x + threadIdx.x;
    // re-zero scratch for next replay (zero-init covers the very first run)
    if (g < N) { g_hist[g] = 0; g_uhist[g] = 0; g_cursor[g] = 0; g_ucursor[g] = 0; }
    if (g < 2 * MAX_BLKS + 2) g_bpack[g] = 0ULL;

    int u = g >> 5;
    int lane = g & 31;
    if (u >= N) return;
    const float2* __restrict__ h2 = (const float2*)g_bufB;
    int beg = g_urowptr[u];
    int cnt = ((u + 1 < N) ? g_urowptr[u + 1] : N) - beg;
    float ax = 0.f, ay = 0.f;
    for (int base = 0; base < cnt; base += 32) {
        int n = cnt - base; if (n > 32) n = 32;
        int node_l = g_unodes[beg + base + ((lane < n) ? lane : 0)];
#pragma unroll 8
        for (int j = 0; j < n; ++j) {
            int node = __shfl_sync(0xffffffffu, node_l, j);
            float2 hs = h2[(size_t)node * 32 + lane];
            ax += hs.x; ay += hs.y;
        }
    }
    float inv = (cnt > 0) ? 1.0f / (float)cnt : 0.f;
    ((float2*)out)[(size_t)u * 32 + lane] = make_float2(ax * inv, ay * inv);
}

// ---------------------------------------------------------------------------
// tf32 tensor-core GEMM, cp.async double-buffered A staging (R13-verified).
// ---------------------------------------------------------------------------
template <int K>
__global__ void __launch_bounds__(256) gemm_kernel(const float* __restrict__ Ax,
                                                   const float* __restrict__ W,
                                                   int in_sel, int N) {
    const float* __restrict__ A = in_sel ? (const float*)g_bufB : Ax;
    __shared__ unsigned int Ws[K][72];                  // tf32 (rna) bits
    __shared__ __align__(16) unsigned int xs[2][128][36]; // raw fp32 bits (as tf32)

    int tid = threadIdx.x;
    int lane = tid & 31;
    int warp = tid >> 5;
    int warpRow = warp >> 1;            // 0..3 -> 32-row strip
    int warpCol = warp & 1;             // 0..1 -> 32-col strip
    int g = lane >> 2;                  // 0..7
    int tig = lane & 3;                 // 0..3
    int row0 = blockIdx.x * 128;
    int base_r = tid >> 3;              // 0..31 (staging row group)
    int kk = (tid & 7) * 4;             // 0..28 (staging k offset)

    // stage W (tf32, rna) once
    for (int i = tid; i < K * 64; i += 256)
        Ws[i >> 6][i & 63] = f2tf32(W[i]);

    const int NC = K / 32;
    // prefetch chunk 0 (OOB rows clamp to a valid address; results discarded)
#pragma unroll
    for (int it = 0; it < 4; ++it) {
        int r = base_r + it * 32;
        int row = row0 + r; if (row >= N) row = N - 1;
        cp_async16(&xs[0][r][kk], A + (size_t)row * K + kk);
    }
    cp_commit();

    float acc[2][4][4];
#pragma unroll
    for (int mi = 0; mi < 2; ++mi)
#pragma unroll
        for (int ni = 0; ni < 4; ++ni)
#pragma unroll
            for (int q = 0; q < 4; ++q) acc[mi][ni][q] = 0.f;

    for (int c = 0; c < NC; ++c) {
        if (c + 1 < NC) {                // prefetch next chunk; overlaps mma
#pragma unroll
            for (int it = 0; it < 4; ++it) {
                int r = base_r + it * 32;
                int row = row0 + r; if (row >= N) row = N - 1;
                cp_async16(&xs[(c + 1) & 1][r][kk],
                           A + (size_t)row * K + (c + 1) * 32 + kk);
            }
            cp_commit();
            cp_wait<1>();                // chunk c arrived (c+1 may be in flight)
        } else {
            cp_wait<0>();
        }
        __syncthreads();
        const unsigned int (*xb)[36] = xs[c & 1];
#pragma unroll
        for (int k8 = 0; k8 < 4; ++k8) {
            int kl = k8 * 8;             // k within chunk (xb)
            int kg = c * 32 + kl;        // k within W (Ws)
            unsigned int a[2][4];
#pragma unroll
            for (int mi = 0; mi < 2; ++mi) {
                int r = warpRow * 32 + mi * 16 + g;
                a[mi][0] = xb[r][kl + tig];
                a[mi][1] = xb[r + 8][kl + tig];
                a[mi][2] = xb[r][kl + tig + 4];
                a[mi][3] = xb[r + 8][kl + tig + 4];
            }
            unsigned int b[4][2];
#pragma unroll
            for (int ni = 0; ni < 4; ++ni) {
                int j = warpCol * 32 + ni * 8 + g;
                b[ni][0] = Ws[kg + tig][j];
                b[ni][1] = Ws[kg + tig + 4][j];
            }
#pragma unroll
            for (int mi = 0; mi < 2; ++mi)
#pragma unroll
                for (int ni = 0; ni < 4; ++ni)
                    mma_tf32(acc[mi][ni], a[mi], b[ni]);
        }
        __syncthreads();                 // buf consumed before it's re-filled
    }

    // epilogue: c0,c1 -> (row g, cols 2tig,2tig+1); c2,c3 -> row g+8
#pragma unroll
    for (int mi = 0; mi < 2; ++mi) {
#pragma unroll
        for (int ni = 0; ni < 4; ++ni) {
            int col = warpCol * 32 + ni * 8 + tig * 2;
            int rA = row0 + warpRow * 32 + mi * 16 + g;
            int rB = rA + 8;
            if (rA < N)
                *(float2*)(&g_bufA[(size_t)rA * 64 + col]) =
                    make_float2(acc[mi][ni][0], acc[mi][ni][1]);
            if (rB < N)
                *(float2*)(&g_bufA[(size_t)rB * 64 + col]) =
                    make_float2(acc[mi][ni][2], acc[mi][ni][3]);
        }
    }
}

// ---------------------------------------------------------------------------
static inline int cdiv(int a, int b) { return (a + b - 1) / b; }

extern "C" void kernel_launch(void* const* d_in, const int* in_sizes, int n_in,
                              void* d_out, int out_size) {
    const float* x    = (const float*)d_in[0];
    const int*   ei   = (const int*)d_in[1];      // int32 per harness dtype contract
    const int*   uidx = (const int*)d_in[2];
    const float* W1   = (const float*)d_in[3];
    const float* b1   = (const float*)d_in[4];
    const float* W2   = (const float*)d_in[5];
    const float* b2   = (const float*)d_in[6];
    float* out = (float*)d_out;

    const int N = in_sizes[2];
    const int E = in_sizes[1] / 2;
    const int* src = ei;
    const int* dst = ei + E;

    const int TB = 256;
    const int nblk = cdiv(N, SCAN_TILE);

    // One-time stream/event setup (first call is the uncaptured correctness
    // run; no device memory is allocated by these).
    static cudaStream_t s2 = nullptr;
    static cudaEvent_t evFork = nullptr, evJoin = nullptr;
    if (s2 == nullptr) {
        cudaStreamCreateWithFlags(&s2, cudaStreamNonBlocking);
        cudaEventCreateWithFlags(&evFork, cudaEventDisableTiming);
        cudaEventCreateWithFlags(&evJoin, cudaEventDisableTiming);
    }

    // ---- fork: CSR build on s2, gemm1 on default stream (independent) ----
    cudaEventRecord(evFork, 0);
    cudaStreamWaitEvent(s2, evFork, 0);

    k_histboth<<<cdiv(E + N, TB), TB, 0, s2>>>(dst, uidx, E, N);
    k_scan<<<2 * nblk, SCAN_TILE, 0, s2>>>(nblk, N);
    k_scatterboth<<<cdiv(E + N, TB), TB, 0, s2>>>(src, dst, uidx, E, N);
    cudaEventRecord(evJoin, s2);

    gemm_kernel<128><<<cdiv(N, 128), 256>>>(x, W1, 0, N);   // x -> bufA

    cudaStreamWaitEvent(0, evJoin, 0);                      // join

    // ---- layer-1 aggregate (bufA -> bufB, +b1, relu, tf32-rounded) ----
    k_aggr<<<cdiv(N * 32, TB), TB>>>(b1, N, E, 1);
    // ---- layer 2 ----
    gemm_kernel<64><<<cdiv(N, 128), 256>>>(x, W2, 1, N);    // bufB -> bufA
    k_aggr<<<cdiv(N * 32, TB), TB>>>(b2, N, E, 0);          // bufA -> bufB
    // ---- scatter-mean (bufB -> out) + scratch re-zero for next replay ----
    k_umean<<<cdiv(N * 32, TB), TB>>>(out, N);
}